// round 17
// baseline (speedup 1.0000x reference)
#include <cuda_runtime.h>

#define HH 1024
#define WW 1536
#define NN (HH*WW)

// 2x2 block grid
#define BW2 768              // WW/2
#define BH2 512              // HH/2
#define NB (BW2*BH2)         // 393216 blocks

// ---------------- device scratch (no allocation allowed) ----------------
// pooled zero-init region: [0,NN)=y2 ; [NN,NN+NB)=cnt ; [NN+NB,NN+2NB)=maxlab
static __device__ int g_pool[NN + 2 * NB];
static __device__ int g_dst[NN];
static __device__ unsigned char g_bpat[NB];   // 4-bit fg pattern per 2x2 block
static __device__ int g_bpar[NB];             // block union-find parents
static __device__ int g_labi[NN];             // root+1 per fg pixel (0 = bg)

// block pattern bits: 0=TL(r0,c0) 1=TR(r0,c1) 2=BL(r1,c0) 3=BR(r1,c1)

__device__ __forceinline__ int dstf(int j, const float* __restrict__ df) {
    float dx = df[j];
    float dy = df[NN + j];
    float l2  = __fadd_rn(__fmul_rn(dx, dx), __fmul_rn(dy, dy));
    float len = __fsqrt_rn(l2);
    float den = __fadd_rn(len, 1e-19f);
    float ux  = __fdiv_rn(dx, den);
    float uy  = __fdiv_rn(dy, den);
    float dfc = fminf(fmaxf(len, 3.0f), 6.0f);
    int r = j / WW;
    int c = j - r * WW;
    float px = __fadd_rn((float)r, __fmul_rn(ux, dfc));
    float py = __fadd_rn((float)c, __fmul_rn(uy, dfc));
    px = fminf(fmaxf(px, 0.0f), (float)(HH - 1));
    py = fminf(fmaxf(py, 0.0f), (float)(WW - 1));
    return __float2int_rn(px) * WW + __float2int_rn(py);   // ties-to-even
}

// ---------------- kernels ----------------

// dst_ids + BOTH scatter-sums fused:
// y2[dst(dst(i))] += fore[i]  (dst recomputed functionally at the hop)
__global__ void k_dst_scat(const float* __restrict__ yh, const float* __restrict__ df,
                           int* __restrict__ dst, int* __restrict__ y2) {
    int q = blockIdx.x * blockDim.x + threadIdx.x;
    if (q >= NN / 4) return;
    int i = q * 4;
    float4 vh = *(const float4*)(yh + i);
    int ds[4];
#pragma unroll
    for (int k = 0; k < 4; k++) ds[k] = dstf(i + k, df);
    int4 d; d.x = ds[0]; d.y = ds[1]; d.z = ds[2]; d.w = ds[3];
    *(int4*)(dst + i) = d;
    float fh[4] = {vh.x, vh.y, vh.z, vh.w};
#pragma unroll
    for (int k = 0; k < 4; k++) {
        if (fh[k] > 0.5f) {
            int dd = dstf(ds[k], df);      // second hop, recomputed from df
            atomicAdd(&y2[dd], 1);
        }
    }
}

// ---- fused avgpool5(count_include_pad=False) + threshold + cross-erosion
//      + 2x2 block pattern packing + block parent init ----
#define TW 32
#define TH 8
__global__ void k_pool_erode(const int* __restrict__ y2,
                             unsigned char* __restrict__ bpat,
                             int* __restrict__ bpar) {
    __shared__ int y2s[14][38];
    __shared__ int css[10][38];
    __shared__ unsigned char m0s[10][36];
    __shared__ unsigned char mes[TH][TW];

    int tx = threadIdx.x, ty = threadIdx.y;
    int tid = ty * TW + tx;
    int gr0 = blockIdx.y * TH;
    int gc0 = blockIdx.x * TW;

    for (int k = tid; k < 14 * 38; k += TW * TH) {
        int rr = k / 38, cc = k % 38;
        int gr = gr0 - 3 + rr, gc = gc0 - 3 + cc;
        y2s[rr][cc] = (gr >= 0 && gr < HH && gc >= 0 && gc < WW) ? y2[gr * WW + gc] : 0;
    }
    __syncthreads();

    for (int k = tid; k < 10 * 38; k += TW * TH) {
        int rr = k / 38, cc = k % 38;
        css[rr][cc] = y2s[rr][cc] + y2s[rr + 1][cc] + y2s[rr + 2][cc]
                    + y2s[rr + 3][cc] + y2s[rr + 4][cc];
    }
    __syncthreads();

    for (int k = tid; k < 10 * 36; k += TW * TH) {
        int rr = k / 36, jj = k % 36;
        int r = gr0 - 1 + rr, c = gc0 - 1 + jj;
        unsigned char m;
        if (r < 0 || r >= HH || c < 0 || c >= WW) {
            m = 1;                                   // pad = foreground
        } else {
            int s = css[rr][jj] + css[rr][jj + 1] + css[rr][jj + 2]
                  + css[rr][jj + 3] + css[rr][jj + 4];
            int rin = min(r + 2, HH - 1) - max(r - 2, 0) + 1;
            int cin = min(c + 2, WW - 1) - max(c - 2, 0) + 1;
            m = (unsigned char)(2 * s >= rin * cin);
        }
        m0s[rr][jj] = m;
    }
    __syncthreads();

    mes[ty][tx] = m0s[ty + 1][tx + 1] & m0s[ty][tx + 1] & m0s[ty + 2][tx + 1]
                & m0s[ty + 1][tx] & m0s[ty + 1][tx + 2];
    __syncthreads();

    if (tid < (TW / 2) * (TH / 2)) {
        int tx2 = tid & (TW / 2 - 1);
        int ty2 = tid >> 4;
        unsigned char p = (unsigned char)(mes[ty2 * 2][tx2 * 2]
                        | (mes[ty2 * 2][tx2 * 2 + 1] << 1)
                        | (mes[ty2 * 2 + 1][tx2 * 2] << 2)
                        | (mes[ty2 * 2 + 1][tx2 * 2 + 1] << 3));
        int gb = ((gr0 >> 1) + ty2) * BW2 + (gc0 >> 1) + tx2;
        bpat[gb] = p;
        bpar[gb] = gb;
    }
}

// find with path halving (parents strictly increasing -> no ABA)
__device__ __forceinline__ int uf_find(int* __restrict__ par, int i) {
    int p = par[i];
    while (true) {
        int pp = par[p];
        if (p == pp) return p;
        par[i] = pp;
        i = p; p = pp;
    }
}

// lock-free union, hook smaller root under larger root.
// Fast path: identical parent values => same root => skip.
__device__ void uf_union(int* __restrict__ par, int a, int b) {
    if (par[a] == par[b]) return;
    while (true) {
        a = uf_find(par, a);
        b = uf_find(par, b);
        if (a == b) return;
        int hi = max(a, b);
        int lo = min(a, b);
        int old = atomicCAS(&par[lo], lo, hi);
        if (old == lo) return;
        a = hi; b = old;
    }
}

// block-level unions: E, S, SW, SE neighbors via pattern bit tests
// bits: 1=TL 2=TR 4=BL 8=BR ; right col=0xA left col=0x5 bottom=0xC top=0x3
__global__ void k_bunion(const unsigned char* __restrict__ bpat, int* __restrict__ bpar) {
    int b = blockIdx.x * blockDim.x + threadIdx.x;
    if (b >= NB) return;
    unsigned p = bpat[b];
    if (!p) return;
    int br = b / BW2, bc = b - br * BW2;
    if (bc < BW2 - 1 && (p & 0xA) && (bpat[b + 1] & 0x5)) uf_union(bpar, b, b + 1);
    if (br < BH2 - 1) {
        if ((p & 0xC) && (bpat[b + BW2] & 0x3))              uf_union(bpar, b, b + BW2);
        if (bc > 0 && (p & 0x4) && (bpat[b + BW2 - 1] & 0x2)) uf_union(bpar, b, b + BW2 - 1);
        if (bc < BW2 - 1 && (p & 0x8) && (bpat[b + BW2 + 1] & 0x1)) uf_union(bpar, b, b + BW2 + 1);
    }
}

// per-component max pixel index via atomicMax on the root
__global__ void k_bmax(const unsigned char* __restrict__ bpat, int* __restrict__ bpar,
                       int* __restrict__ maxlab) {
    int b = blockIdx.x * blockDim.x + threadIdx.x;
    if (b >= NB) return;
    unsigned p = bpat[b];
    if (!p) return;
    int br = b / BW2, bc = b - br * BW2;
    int r0 = br * 2, c0 = bc * 2;
    int m;
    if      (p & 8) m = (r0 + 1) * WW + c0 + 1;
    else if (p & 4) m = (r0 + 1) * WW + c0;
    else if (p & 2) m = r0 * WW + c0 + 1;
    else            m = r0 * WW + c0;
    int rt = uf_find(bpar, b);
    atomicMax(&maxlab[rt], m);
}

// labi[i] = root+1 of component of dst^8(i) (0 if bg); cnt indexed by root
__global__ void k_labi(const float* __restrict__ yh, const int* __restrict__ dst,
                       const unsigned char* __restrict__ bpat, int* __restrict__ bpar,
                       int* __restrict__ labi, int* __restrict__ cnt) {
    int i = blockIdx.x * blockDim.x + threadIdx.x;   // grid exact: NN % 256 == 0
    int la = 0;
    if (yh[i] > 0.5f) {
        int j = i;
#pragma unroll
        for (int h = 0; h < 8; h++) j = dst[j];
        int r = j / WW, c = j - r * WW;
        int bj = (r >> 1) * BW2 + (c >> 1);
        int bit = ((r & 1) << 1) | (c & 1);
        if ((bpat[bj] >> bit) & 1)
            la = uf_find(bpar, bj) + 1;
    }
    labi[i] = la;
    unsigned peers = __match_any_sync(0xffffffffu, la);
    int lane = threadIdx.x & 31;
    if (la > 0 && (__ffs(peers) - 1) == lane)
        atomicAdd(&cnt[la - 1], __popc(peers));
}

// keep components with size > 256; value = maxlab[root]+1
__global__ void k_final(const int* __restrict__ labi, const int* __restrict__ cnt,
                        const int* __restrict__ maxlab, float* __restrict__ out) {
    int q = blockIdx.x * blockDim.x + threadIdx.x;
    if (q >= NN / 4) return;
    int i = q * 4;
    int4 la = *(const int4*)(labi + i);
    float4 o;
    o.x = (la.x > 0 && cnt[la.x - 1] > 256) ? (float)(maxlab[la.x - 1] + 1) : 0.0f;
    o.y = (la.y > 0 && cnt[la.y - 1] > 256) ? (float)(maxlab[la.y - 1] + 1) : 0.0f;
    o.z = (la.z > 0 && cnt[la.z - 1] > 256) ? (float)(maxlab[la.z - 1] + 1) : 0.0f;
    o.w = (la.w > 0 && cnt[la.w - 1] > 256) ? (float)(maxlab[la.w - 1] + 1) : 0.0f;
    *(float4*)(out + i) = o;
}

// ---------------- launcher ----------------
extern "C" void kernel_launch(void* const* d_in, const int* in_sizes, int n_in,
                              void* d_out, int out_size) {
    const float* y_hat;
    const float* df;
    if (in_sizes[0] == NN) { y_hat = (const float*)d_in[0]; df = (const float*)d_in[1]; }
    else                   { df = (const float*)d_in[0]; y_hat = (const float*)d_in[1]; }
    float* out = (float*)d_out;

    void *ppool, *pdst, *pbpat, *pbpar, *plabi;
    cudaGetSymbolAddress(&ppool, g_pool);
    cudaGetSymbolAddress(&pdst, g_dst);
    cudaGetSymbolAddress(&pbpat, g_bpat);
    cudaGetSymbolAddress(&pbpar, g_bpar);
    cudaGetSymbolAddress(&plabi, g_labi);

    int* y2     = (int*)ppool;
    int* cnt    = y2 + NN;              // NB ints, indexed by block root
    int* maxlab = y2 + NN + NB;         // NB ints

    cudaMemsetAsync(ppool, 0, (size_t)(NN + 2 * NB) * 4, 0);

    const int B = 256;
    const int G  = (NN + B - 1) / B;
    const int G4 = (NN / 4 + B - 1) / B;
    const int GB = (NB + B - 1) / B;

    k_dst_scat<<<G4, B>>>(y_hat, df, (int*)pdst, y2);
    {
        dim3 blk(TW, TH);
        dim3 grd(WW / TW, HH / TH);
        k_pool_erode<<<grd, blk>>>(y2, (unsigned char*)pbpat, (int*)pbpar);
    }
    k_bunion<<<GB, B>>>((const unsigned char*)pbpat, (int*)pbpar);
    k_bmax<<<GB, B>>>((const unsigned char*)pbpat, (int*)pbpar, maxlab);
    k_labi<<<G, B>>>(y_hat, (const int*)pdst, (const unsigned char*)pbpat,
                     (int*)pbpar, (int*)plabi, cnt);
    k_final<<<G4, B>>>((const int*)plabi, cnt, maxlab, out);
}